// round 11
// baseline (speedup 1.0000x reference)
#include <cuda_runtime.h>
#include <cuda_fp16.h>

#define D 16
#define NMAX 100000
#define CAP 128          // max per-node in-degree bucket (Poisson(32) max ~65)

// Scratch (static __device__). Referenced ONLY from device code.
__device__ uint4    g_fsh[NMAX * 2];   // layer-1 feat_src fp16 (32B/row)
__device__ float4   g_fd[NMAX * 4];    // layer-1 feat_dst fp32
__device__ uint4    g_fshB[NMAX * 2];  // layer-2 feat_src fp16 (written by accum1)
__device__ float4   g_fdB[NMAX * 4];   // layer-2 feat_dst fp32 (written by accum1)
__device__ int      g_cnt[NMAX];       // per-dst edge count
__device__ int      g_esrc[NMAX * CAP];// bucketed src indices: node n -> [n*CAP, n*CAP+cnt)

__device__ __forceinline__ float lr02(float x)  { return x > 0.f ? x : 0.2f  * x; }
__device__ __forceinline__ float lr001(float x) { return x > 0.f ? x : 0.01f * x; }

// ---------------------------------------------------------------------------
// feat: fs1 = emb@Ws1+bs1 (fp16), fd1 = emb@Wd1+bd1 (fp32). Zeroes g_cnt.
// ---------------------------------------------------------------------------
__global__ __launch_bounds__(256) void feat_kernel(
        const float* __restrict__ h,
        const float* __restrict__ Wsrc, const float* __restrict__ bsrc,
        const float* __restrict__ Wdst, const float* __restrict__ bdst,
        int N) {
    __shared__ float sWs[D * D], sWd[D * D], sbs[D], sbd[D];
    int tid = threadIdx.x;
    if (tid < D * D) { sWs[tid] = Wsrc[tid]; sWd[tid] = Wdst[tid]; }
    if (tid < D)     { sbs[tid] = bsrc[tid]; sbd[tid] = bdst[tid]; }
    __syncthreads();

    int n = blockIdx.x * blockDim.x + tid;
    if (n >= N) return;

    const float4* h4 = (const float4*)h + n * 4;
    float hr[D];
#pragma unroll
    for (int i = 0; i < 4; i++) {
        float4 v = h4[i];
        hr[4 * i + 0] = v.x; hr[4 * i + 1] = v.y; hr[4 * i + 2] = v.z; hr[4 * i + 3] = v.w;
    }
    float os[D], od[D];
#pragma unroll
    for (int j = 0; j < D; j++) { os[j] = sbs[j]; od[j] = sbd[j]; }
#pragma unroll
    for (int k = 0; k < D; k++) {
        float hv = hr[k];
#pragma unroll
        for (int j = 0; j < D; j++) {
            os[j] = fmaf(hv, sWs[k * D + j], os[j]);
            od[j] = fmaf(hv, sWd[k * D + j], od[j]);
        }
    }
    uint4 p0, p1;
    {
        __half2 t;
        t = __floats2half2_rn(os[0],  os[1]);  p0.x = *reinterpret_cast<unsigned*>(&t);
        t = __floats2half2_rn(os[2],  os[3]);  p0.y = *reinterpret_cast<unsigned*>(&t);
        t = __floats2half2_rn(os[4],  os[5]);  p0.z = *reinterpret_cast<unsigned*>(&t);
        t = __floats2half2_rn(os[6],  os[7]);  p0.w = *reinterpret_cast<unsigned*>(&t);
        t = __floats2half2_rn(os[8],  os[9]);  p1.x = *reinterpret_cast<unsigned*>(&t);
        t = __floats2half2_rn(os[10], os[11]); p1.y = *reinterpret_cast<unsigned*>(&t);
        t = __floats2half2_rn(os[12], os[13]); p1.z = *reinterpret_cast<unsigned*>(&t);
        t = __floats2half2_rn(os[14], os[15]); p1.w = *reinterpret_cast<unsigned*>(&t);
    }
    g_fsh[n * 2 + 0] = p0;
    g_fsh[n * 2 + 1] = p1;
#pragma unroll
    for (int i = 0; i < 4; i++)
        g_fd[n * 4 + i] = make_float4(od[4 * i], od[4 * i + 1], od[4 * i + 2], od[4 * i + 3]);
    g_cnt[n] = 0;
}

// ---------------------------------------------------------------------------
// build: fused rank+scatter into fixed-capacity buckets. One pass per layer.
//   r = atomicAdd(cnt[dst]); esrc[dst*CAP + r] = src   (8 edges/thread, MLP=8)
// ---------------------------------------------------------------------------
__global__ __launch_bounds__(256) void build_kernel(
        const int* __restrict__ src, const int* __restrict__ dst, int E) {
    int i = blockIdx.x * blockDim.x + threadIdx.x;
    int e = i * 8;
    if (e + 7 < E) {
        int4 s0 = reinterpret_cast<const int4*>(src)[i * 2];
        int4 s1 = reinterpret_cast<const int4*>(src)[i * 2 + 1];
        int4 d0 = reinterpret_cast<const int4*>(dst)[i * 2];
        int4 d1 = reinterpret_cast<const int4*>(dst)[i * 2 + 1];
        int r0 = atomicAdd(&g_cnt[d0.x], 1);
        int r1 = atomicAdd(&g_cnt[d0.y], 1);
        int r2 = atomicAdd(&g_cnt[d0.z], 1);
        int r3 = atomicAdd(&g_cnt[d0.w], 1);
        int r4 = atomicAdd(&g_cnt[d1.x], 1);
        int r5 = atomicAdd(&g_cnt[d1.y], 1);
        int r6 = atomicAdd(&g_cnt[d1.z], 1);
        int r7 = atomicAdd(&g_cnt[d1.w], 1);
        if (r0 < CAP) g_esrc[d0.x * CAP + r0] = s0.x;
        if (r1 < CAP) g_esrc[d0.y * CAP + r1] = s0.y;
        if (r2 < CAP) g_esrc[d0.z * CAP + r2] = s0.z;
        if (r3 < CAP) g_esrc[d0.w * CAP + r3] = s0.w;
        if (r4 < CAP) g_esrc[d1.x * CAP + r4] = s1.x;
        if (r5 < CAP) g_esrc[d1.y * CAP + r5] = s1.y;
        if (r6 < CAP) g_esrc[d1.z * CAP + r6] = s1.z;
        if (r7 < CAP) g_esrc[d1.w * CAP + r7] = s1.w;
    } else {
        for (; e < E; e++) {
            int d = dst[e];
            int r = atomicAdd(&g_cnt[d], 1);
            if (r < CAP) g_esrc[d * CAP + r] = src[e];
        }
    }
}

// ---------------------------------------------------------------------------
// Accumulate: half-warp (16 lanes) per node, LANE-PAIRED gathers.
//   pair p = sub>>1 handles edges p, p+8, ... of the node's bucket.
//   half = sub&1 selects the 16B half (dims [half*8, half*8+8)) of the fs row.
//   Loop trip count is WARP-UNIFORM (max over both nodes); invalid iterations
//   use clamped index and force sc = -1e30 -> exp = 0 (no contribution).
//   Both lanes of a pair add ex to den -> den = 2*sum -> inv = 2/den.
// After the 3-stage exchange reduction, lane `sub` holds feature component
//   dim(sub) = 8*(sub&1) + 4*bit3(sub) + 2*bit2(sub) + bit1(sub)  in acc[0].
// ---------------------------------------------------------------------------
#define ACCUM_BODY(FS_TABLE, FD_TABLE)                                         \
    int gw = (blockIdx.x * 256 + threadIdx.x) >> 5;                            \
    int lane = threadIdx.x & 31;                                               \
    int sub = lane & 15;                                                       \
    int half = sub & 1;                                                        \
    int pairi = sub >> 1;                                                      \
    int node = gw * 2 + (lane >> 4);                                           \
    int beg = 0, deg = 0;                                                      \
    if (node < N) { beg = node * CAP; deg = min(g_cnt[node], CAP); }           \
    int end = beg + deg;                                                       \
    int nIt = (deg + 7) >> 3;                                                  \
    _Pragma("unroll")                                                          \
    for (int o = 16; o >= 1; o >>= 1)                                          \
        nIt = max(nIt, __shfl_xor_sync(0xffffffffu, nIt, o));                  \
    float bb[8];                                                               \
    if (node < N) {                                                            \
        const float4* f4 = FD_TABLE + node * 4 + half * 2;                     \
        float4 v0 = f4[0], v1 = f4[1];                                         \
        bb[0] = v0.x; bb[1] = v0.y; bb[2] = v0.z; bb[3] = v0.w;                \
        bb[4] = v1.x; bb[5] = v1.y; bb[6] = v1.z; bb[7] = v1.w;                \
    } else {                                                                   \
        _Pragma("unroll")                                                      \
        for (int j = 0; j < 8; j++) bb[j] = 0.f;                               \
    }                                                                          \
    float at8[8];                                                              \
    _Pragma("unroll")                                                          \
    for (int j = 0; j < 8; j++) at8[j] = sat[half * 8 + j];                    \
    float acc[8];                                                              \
    _Pragma("unroll")                                                          \
    for (int j = 0; j < 8; j++) acc[j] = 0.f;                                  \
    float den = 0.f;                                                           \
    for (int i2 = 0; i2 < nIt; i2++) {                                         \
        int idx = beg + pairi + i2 * 8;                                        \
        bool valid = (idx < end);                                              \
        int sidx = valid ? idx : beg;                                          \
        int s = g_esrc[sidx];                                                  \
        uint4 r0 = FS_TABLE[s * 2 + half];                                     \
        float a[8];                                                            \
        float2 f;                                                              \
        f = __half22float2(*reinterpret_cast<__half2*>(&r0.x)); a[0]=f.x; a[1]=f.y; \
        f = __half22float2(*reinterpret_cast<__half2*>(&r0.y)); a[2]=f.x; a[3]=f.y; \
        f = __half22float2(*reinterpret_cast<__half2*>(&r0.z)); a[4]=f.x; a[5]=f.y; \
        f = __half22float2(*reinterpret_cast<__half2*>(&r0.w)); a[6]=f.x; a[7]=f.y; \
        float sc = valid ? 0.f : -1e30f;                                       \
        _Pragma("unroll")                                                      \
        for (int j = 0; j < 8; j++) sc = fmaf(lr02(a[j] + bb[j]), at8[j], sc); \
        sc += __shfl_xor_sync(0xffffffffu, sc, 1);                             \
        float ex = __expf(sc);                                                 \
        den += ex;                                                             \
        _Pragma("unroll")                                                      \
        for (int j = 0; j < 8; j++) acc[j] = fmaf(ex, a[j], acc[j]);           \
    }                                                                          \
    _Pragma("unroll")                                                          \
    for (int o = 8; o >= 1; o >>= 1) den += __shfl_xor_sync(0xffffffffu, den, o); \
    _Pragma("unroll")                                                          \
    for (int j = 0; j < 4; j++) {                                              \
        float send = (lane & 8) ? acc[j] : acc[j + 4];                         \
        float recv = __shfl_xor_sync(0xffffffffu, send, 8);                    \
        acc[j] = ((lane & 8) ? acc[j + 4] : acc[j]) + recv;                    \
    }                                                                          \
    _Pragma("unroll")                                                          \
    for (int j = 0; j < 2; j++) {                                              \
        float send = (lane & 4) ? acc[j] : acc[j + 2];                         \
        float recv = __shfl_xor_sync(0xffffffffu, send, 4);                    \
        acc[j] = ((lane & 4) ? acc[j + 2] : acc[j]) + recv;                    \
    }                                                                          \
    {                                                                          \
        float send = (lane & 2) ? acc[0] : acc[1];                             \
        float recv = __shfl_xor_sync(0xffffffffu, send, 2);                    \
        acc[0] = ((lane & 2) ? acc[1] : acc[0]) + recv;                        \
    }                                                                          \
    int dim = (half << 3) | (((sub >> 3) & 1) << 2) | (((sub >> 2) & 1) << 1) | ((sub >> 1) & 1); \
    float inv = (den > 0.f) ? (2.0f / den) : 0.f;                              \
    float val = lr001(acc[0] * inv);

// inverse lane permutation: lane (within half-warp) holding component k
#define INV_LANE(k) ((((k) >> 2) & 1) * 8 + (((k) >> 1) & 1) * 4 + ((k) & 1) * 2 + (((k) >> 3) & 1))

// layer-1 accumulate, fused with layer-2 feature projection
__global__ __launch_bounds__(256) void accum1_kernel(
        const float* __restrict__ attn,
        const float* __restrict__ Ws2, const float* __restrict__ bs2,
        const float* __restrict__ Wd2, const float* __restrict__ bd2,
        int N) {
    __shared__ float sat[D];
    __shared__ float sWs[D * D], sWd[D * D], sbs[D], sbd[D];
    if (threadIdx.x < D) {
        sat[threadIdx.x] = attn[threadIdx.x];
        sbs[threadIdx.x] = bs2[threadIdx.x];
        sbd[threadIdx.x] = bd2[threadIdx.x];
    }
    if (threadIdx.x < D * D) { sWs[threadIdx.x] = Ws2[threadIdx.x]; sWd[threadIdx.x] = Wd2[threadIdx.x]; }
    __syncthreads();

    ACCUM_BODY(g_fsh, g_fd)

    // fused layer-2 projection: component k of h2 lives on lane INV_LANE(k)
    float os = sbs[sub], od = sbd[sub];
#pragma unroll
    for (int k = 0; k < D; k++) {
        float h2k = __shfl_sync(0xffffffffu, val, (lane & 16) + INV_LANE(k));
        os = fmaf(h2k, sWs[k * D + sub], os);
        od = fmaf(h2k, sWd[k * D + sub], od);
    }
    float osn = __shfl_xor_sync(0xffffffffu, os, 1);
    if (node < N) {
        if (!(sub & 1)) {
            __half2 t = __floats2half2_rn(os, osn);
            reinterpret_cast<unsigned*>(g_fshB)[node * 8 + (sub >> 1)] = *reinterpret_cast<unsigned*>(&t);
        }
        reinterpret_cast<float*>(g_fdB)[node * D + sub] = od;
        if (sub == 0) g_cnt[node] = 0;   // reset histogram for layer 2
    }
}

// layer-2 accumulate: writes final output
__global__ __launch_bounds__(256) void accum2_kernel(
        const float* __restrict__ attn, float* __restrict__ out, int N) {
    __shared__ float sat[D];
    if (threadIdx.x < D) sat[threadIdx.x] = attn[threadIdx.x];
    __syncthreads();

    ACCUM_BODY(g_fshB, g_fdB)

    if (node < N) out[node * D + dim] = val;
}

// ---------------------------------------------------------------------------
// launch
// ---------------------------------------------------------------------------
extern "C" void kernel_launch(void* const* d_in, const int* in_sizes, int n_in,
                              void* d_out, int out_size) {
    const float* emb  = (const float*)d_in[0];
    const int*   src1 = (const int*)d_in[1];
    const int*   dst1 = (const int*)d_in[2];
    const int*   src2 = (const int*)d_in[3];
    const int*   dst2 = (const int*)d_in[4];
    const float* Ws1  = (const float*)d_in[5];
    const float* bs1  = (const float*)d_in[6];
    const float* Wd1  = (const float*)d_in[7];
    const float* bd1  = (const float*)d_in[8];
    const float* at1  = (const float*)d_in[9];
    const float* Ws2  = (const float*)d_in[10];
    const float* bs2  = (const float*)d_in[11];
    const float* Wd2  = (const float*)d_in[12];
    const float* bd2  = (const float*)d_in[13];
    const float* at2  = (const float*)d_in[14];

    int N  = in_sizes[0] / D;
    int E1 = in_sizes[1];
    int E2 = in_sizes[3];

    int nbN  = (N + 255) / 256;
    int nbV1 = ((E1 + 7) / 8 + 255) / 256;     // 8 edges/thread
    int nbV2 = ((E2 + 7) / 8 + 255) / 256;
    int nbA  = (N + 15) / 16;                  // 2 nodes/warp

    // ---- Layer 1 ----
    feat_kernel<<<nbN, 256>>>(emb, Ws1, bs1, Wd1, bd1, N);
    build_kernel<<<nbV1, 256>>>(src1, dst1, E1);
    accum1_kernel<<<nbA, 256>>>(at1, Ws2, bs2, Wd2, bd2, N);

    // ---- Layer 2 ----
    build_kernel<<<nbV2, 256>>>(src2, dst2, E2);
    accum2_kernel<<<nbA, 256>>>(at2, (float*)d_out, N);
}

// round 12
// speedup vs baseline: 1.2723x; 1.2723x over previous
#include <cuda_runtime.h>
#include <cuda_fp16.h>

#define D 16
#define NMAX 100000
#define EMAX 3400000
#define SCAN_BLK 512

// Scratch (static __device__). Referenced from device code; host uses only
// cudaGetSymbolAddress + cudaMemsetAsync (no allocation).
__device__ uint4    g_fsh[NMAX * 2];   // layer-1 feat_src fp16 (32B/row)
__device__ float4   g_fd[NMAX * 4];    // layer-1 feat_dst fp32
__device__ uint4    g_fshB[NMAX * 2];  // layer-2 feat_src fp16 (written by accum1)
__device__ float4   g_fdB[NMAX * 4];   // layer-2 feat_dst fp32 (written by accum1)
__device__ int      g_cnt1[NMAX], g_cnt2[NMAX];   // per-layer histograms
__device__ int      g_ptr[NMAX + 1];   // CSR row pointers (reused per layer)
__device__ int      g_rank[EMAX];      // per-edge rank (reused per layer)
__device__ int      g_esrc[EMAX];      // src sorted by dst (reused per layer)
__device__ unsigned g_state1[1024], g_state2[1024];  // lookback scan states

__device__ __forceinline__ float lr02(float x)  { return x > 0.f ? x : 0.2f  * x; }
__device__ __forceinline__ float lr001(float x) { return x > 0.f ? x : 0.01f * x; }

// ---------------------------------------------------------------------------
// rank role: hist + per-edge rank via atomic return; 8 edges/thread
// ---------------------------------------------------------------------------
__device__ __forceinline__ void rank_edges(const int* __restrict__ dst, int E,
                                           int* __restrict__ cnt, int b) {
    int i = b * 256 + threadIdx.x;
    int e = i * 8;
    if (e + 7 < E) {
        int4 d0 = reinterpret_cast<const int4*>(dst)[i * 2];
        int4 d1 = reinterpret_cast<const int4*>(dst)[i * 2 + 1];
        int4 r0, r1;
        r0.x = atomicAdd(&cnt[d0.x], 1);
        r0.y = atomicAdd(&cnt[d0.y], 1);
        r0.z = atomicAdd(&cnt[d0.z], 1);
        r0.w = atomicAdd(&cnt[d0.w], 1);
        r1.x = atomicAdd(&cnt[d1.x], 1);
        r1.y = atomicAdd(&cnt[d1.y], 1);
        r1.z = atomicAdd(&cnt[d1.z], 1);
        r1.w = atomicAdd(&cnt[d1.w], 1);
        reinterpret_cast<int4*>(g_rank)[i * 2]     = r0;
        reinterpret_cast<int4*>(g_rank)[i * 2 + 1] = r1;
    } else {
        for (; e < E; e++) g_rank[e] = atomicAdd(&cnt[dst[e]], 1);
    }
}

// ---------------------------------------------------------------------------
// featrank: blocks [0,nbF) compute feat projections; rest do rank on layer 1.
// ---------------------------------------------------------------------------
__global__ __launch_bounds__(256) void featrank_kernel(
        const float* __restrict__ h,
        const float* __restrict__ Wsrc, const float* __restrict__ bsrc,
        const float* __restrict__ Wdst, const float* __restrict__ bdst,
        const int* __restrict__ dst1, int E1, int N, int nbF) {
    if (blockIdx.x >= nbF) {                 // whole block takes rank role
        rank_edges(dst1, E1, g_cnt1, blockIdx.x - nbF);
        return;
    }
    __shared__ float sWs[D * D], sWd[D * D], sbs[D], sbd[D];
    int tid = threadIdx.x;
    if (tid < D * D) { sWs[tid] = Wsrc[tid]; sWd[tid] = Wdst[tid]; }
    if (tid < D)     { sbs[tid] = bsrc[tid]; sbd[tid] = bdst[tid]; }
    __syncthreads();

    int n = blockIdx.x * 256 + tid;
    if (n >= N) return;

    const float4* h4 = (const float4*)h + n * 4;
    float hr[D];
#pragma unroll
    for (int i = 0; i < 4; i++) {
        float4 v = h4[i];
        hr[4 * i + 0] = v.x; hr[4 * i + 1] = v.y; hr[4 * i + 2] = v.z; hr[4 * i + 3] = v.w;
    }
    float os[D], od[D];
#pragma unroll
    for (int j = 0; j < D; j++) { os[j] = sbs[j]; od[j] = sbd[j]; }
#pragma unroll
    for (int k = 0; k < D; k++) {
        float hv = hr[k];
#pragma unroll
        for (int j = 0; j < D; j++) {
            os[j] = fmaf(hv, sWs[k * D + j], os[j]);
            od[j] = fmaf(hv, sWd[k * D + j], od[j]);
        }
    }
    uint4 p0, p1;
    {
        __half2 t;
        t = __floats2half2_rn(os[0],  os[1]);  p0.x = *reinterpret_cast<unsigned*>(&t);
        t = __floats2half2_rn(os[2],  os[3]);  p0.y = *reinterpret_cast<unsigned*>(&t);
        t = __floats2half2_rn(os[4],  os[5]);  p0.z = *reinterpret_cast<unsigned*>(&t);
        t = __floats2half2_rn(os[6],  os[7]);  p0.w = *reinterpret_cast<unsigned*>(&t);
        t = __floats2half2_rn(os[8],  os[9]);  p1.x = *reinterpret_cast<unsigned*>(&t);
        t = __floats2half2_rn(os[10], os[11]); p1.y = *reinterpret_cast<unsigned*>(&t);
        t = __floats2half2_rn(os[12], os[13]); p1.z = *reinterpret_cast<unsigned*>(&t);
        t = __floats2half2_rn(os[14], os[15]); p1.w = *reinterpret_cast<unsigned*>(&t);
    }
    g_fsh[n * 2 + 0] = p0;
    g_fsh[n * 2 + 1] = p1;
#pragma unroll
    for (int i = 0; i < 4; i++)
        g_fd[n * 4 + i] = make_float4(od[4 * i], od[4 * i + 1], od[4 * i + 2], od[4 * i + 3]);
}

// ---------------------------------------------------------------------------
// single-pass lookback scan (layer selects cnt/state arrays)
// ---------------------------------------------------------------------------
__global__ __launch_bounds__(SCAN_BLK) void scan_kernel(int N, int E, int layer) {
    __shared__ int swarp[SCAN_BLK / 32];
    __shared__ unsigned sRun;
    const int* cnt = layer ? g_cnt2 : g_cnt1;
    unsigned* state = layer ? g_state2 : g_state1;
    int tid = threadIdx.x, lane = tid & 31, wid = tid >> 5;
    int bid = blockIdx.x;
    int i = bid * SCAN_BLK + tid;
    if (bid == 0 && tid == 0) g_ptr[N] = E;

    int v = (i < N) ? cnt[i] : 0;
    int x = v;
#pragma unroll
    for (int o = 1; o < 32; o <<= 1) {
        int y = __shfl_up_sync(0xffffffffu, x, o);
        if (lane >= o) x += y;
    }
    if (lane == 31) swarp[wid] = x;
    __syncthreads();
    if (wid == 0) {
        int s = (lane < SCAN_BLK / 32) ? swarp[lane] : 0;
#pragma unroll
        for (int o = 1; o < SCAN_BLK / 32; o <<= 1) {
            int y = __shfl_up_sync(0xffffffffu, s, o);
            if (lane >= o) s += y;
        }
        if (lane < SCAN_BLK / 32) swarp[lane] = s;
    }
    __syncthreads();
    int woff = wid ? swarp[wid - 1] : 0;
    int excl = x - v + woff;
    unsigned A = (unsigned)swarp[SCAN_BLK / 32 - 1];

    if (wid == 0) {
        if (lane == 0) atomicExch(&state[bid], (1u << 30) | A);
        unsigned run = 0;
        int p = bid - 1;
        while (p >= 0) {
            int idx = p - lane;
            unsigned s;
            if (idx >= 0) {
                volatile unsigned* ps = (volatile unsigned*)&state[idx];
                do { s = *ps; } while ((s >> 30) == 0);
            } else {
                s = (2u << 30);
            }
            unsigned flag = s >> 30;
            unsigned val = s & 0x3FFFFFFFu;
            unsigned pm = __ballot_sync(0xffffffffu, flag >= 2);
            int fp_ = pm ? (__ffs(pm) - 1) : 32;
            unsigned c = (lane <= fp_) ? val : 0;
#pragma unroll
            for (int o = 16; o >= 1; o >>= 1) c += __shfl_xor_sync(0xffffffffu, c, o);
            run += c;
            if (pm) break;
            p -= 32;
        }
        if (lane == 0) {
            atomicExch(&state[bid], (2u << 30) | ((run + A) & 0x3FFFFFFFu));
            sRun = run;
        }
    }
    __syncthreads();
    if (i < N) g_ptr[i] = excl + (int)sRun;
}

// ---------------------------------------------------------------------------
// scatter: pos = ptr[dst] + rank; 8 edges/thread
// ---------------------------------------------------------------------------
__global__ __launch_bounds__(256) void scatter_kernel(
        const int* __restrict__ src, const int* __restrict__ dst, int E) {
    int i = blockIdx.x * blockDim.x + threadIdx.x;
    int e = i * 8;
    if (e + 7 < E) {
        int4 s0 = reinterpret_cast<const int4*>(src)[i * 2];
        int4 s1 = reinterpret_cast<const int4*>(src)[i * 2 + 1];
        int4 d0 = reinterpret_cast<const int4*>(dst)[i * 2];
        int4 d1 = reinterpret_cast<const int4*>(dst)[i * 2 + 1];
        int4 r0 = reinterpret_cast<const int4*>(g_rank)[i * 2];
        int4 r1 = reinterpret_cast<const int4*>(g_rank)[i * 2 + 1];
        int p0 = g_ptr[d0.x], p1 = g_ptr[d0.y], p2 = g_ptr[d0.z], p3 = g_ptr[d0.w];
        int p4 = g_ptr[d1.x], p5 = g_ptr[d1.y], p6 = g_ptr[d1.z], p7 = g_ptr[d1.w];
        g_esrc[p0 + r0.x] = s0.x;
        g_esrc[p1 + r0.y] = s0.y;
        g_esrc[p2 + r0.z] = s0.z;
        g_esrc[p3 + r0.w] = s0.w;
        g_esrc[p4 + r1.x] = s1.x;
        g_esrc[p5 + r1.y] = s1.y;
        g_esrc[p6 + r1.z] = s1.z;
        g_esrc[p7 + r1.w] = s1.w;
    } else {
        for (; e < E; e++) g_esrc[g_ptr[dst[e]] + g_rank[e]] = src[e];
    }
}

// ---------------------------------------------------------------------------
// Accumulate body: half-warp per node, lane-paired gathers, 2x unrolled.
//   Both sub-iterations execute unconditionally (validity via predicates),
//   so the pair-exchange shuffles stay warp-uniform. Invalid edges get
//   sc = -1e30 -> exp = 0. den counts each edge twice -> inv = 2/den.
// After the 3-stage exchange reduction, lane `sub` holds feature component
//   dim(sub) = 8*bit0 + 4*bit3 + 2*bit2 + bit1  in acc[0].
// ---------------------------------------------------------------------------
#define UNPACK8(R, A)                                                          \
    { float2 f;                                                                \
      f = __half22float2(*reinterpret_cast<__half2*>(&R.x)); A[0]=f.x; A[1]=f.y; \
      f = __half22float2(*reinterpret_cast<__half2*>(&R.y)); A[2]=f.x; A[3]=f.y; \
      f = __half22float2(*reinterpret_cast<__half2*>(&R.z)); A[4]=f.x; A[5]=f.y; \
      f = __half22float2(*reinterpret_cast<__half2*>(&R.w)); A[6]=f.x; A[7]=f.y; }

#define ACCUM_BODY(FS_TABLE, FD_TABLE)                                         \
    int gw = (blockIdx.x * 256 + threadIdx.x) >> 5;                            \
    int lane = threadIdx.x & 31;                                               \
    int sub = lane & 15;                                                       \
    int half = sub & 1;                                                        \
    int pairi = sub >> 1;                                                      \
    int node = gw * 2 + (lane >> 4);                                           \
    int beg = 0, end = 0;                                                      \
    if (node < N) { beg = g_ptr[node]; end = g_ptr[node + 1]; }                \
    int nIt = (end - beg + 7) >> 3;                                            \
    _Pragma("unroll")                                                          \
    for (int o = 16; o >= 1; o >>= 1)                                          \
        nIt = max(nIt, __shfl_xor_sync(0xffffffffu, nIt, o));                  \
    float bb[8];                                                               \
    if (node < N) {                                                            \
        const float4* f4 = FD_TABLE + node * 4 + half * 2;                     \
        float4 v0 = f4[0], v1 = f4[1];                                         \
        bb[0] = v0.x; bb[1] = v0.y; bb[2] = v0.z; bb[3] = v0.w;                \
        bb[4] = v1.x; bb[5] = v1.y; bb[6] = v1.z; bb[7] = v1.w;                \
    } else {                                                                   \
        _Pragma("unroll")                                                      \
        for (int j = 0; j < 8; j++) bb[j] = 0.f;                               \
    }                                                                          \
    float at8[8];                                                              \
    _Pragma("unroll")                                                          \
    for (int j = 0; j < 8; j++) at8[j] = sat[half * 8 + j];                    \
    float acc[8];                                                              \
    _Pragma("unroll")                                                          \
    for (int j = 0; j < 8; j++) acc[j] = 0.f;                                  \
    float den = 0.f;                                                           \
    for (int i2 = 0; i2 < nIt; i2 += 2) {                                      \
        int idxA = beg + pairi + i2 * 8;                                       \
        int idxB = idxA + 8;                                                   \
        bool vA = (idxA < end), vB = (idxB < end);                             \
        int sA = g_esrc[vA ? idxA : beg];                                      \
        int sB = g_esrc[vB ? idxB : beg];                                      \
        uint4 rA = FS_TABLE[sA * 2 + half];                                    \
        uint4 rB = FS_TABLE[sB * 2 + half];                                    \
        float aA[8], aB[8];                                                    \
        UNPACK8(rA, aA)                                                        \
        UNPACK8(rB, aB)                                                        \
        float scA = vA ? 0.f : -1e30f;                                         \
        float scB = vB ? 0.f : -1e30f;                                         \
        _Pragma("unroll")                                                      \
        for (int j = 0; j < 8; j++) {                                          \
            scA = fmaf(lr02(aA[j] + bb[j]), at8[j], scA);                      \
            scB = fmaf(lr02(aB[j] + bb[j]), at8[j], scB);                      \
        }                                                                      \
        scA += __shfl_xor_sync(0xffffffffu, scA, 1);                           \
        scB += __shfl_xor_sync(0xffffffffu, scB, 1);                           \
        float exA = __expf(scA);                                               \
        float exB = __expf(scB);                                               \
        den += exA + exB;                                                      \
        _Pragma("unroll")                                                      \
        for (int j = 0; j < 8; j++)                                            \
            acc[j] = fmaf(exA, aA[j], fmaf(exB, aB[j], acc[j]));               \
    }                                                                          \
    _Pragma("unroll")                                                          \
    for (int o = 8; o >= 1; o >>= 1) den += __shfl_xor_sync(0xffffffffu, den, o); \
    _Pragma("unroll")                                                          \
    for (int j = 0; j < 4; j++) {                                              \
        float send = (lane & 8) ? acc[j] : acc[j + 4];                         \
        float recv = __shfl_xor_sync(0xffffffffu, send, 8);                    \
        acc[j] = ((lane & 8) ? acc[j + 4] : acc[j]) + recv;                    \
    }                                                                          \
    _Pragma("unroll")                                                          \
    for (int j = 0; j < 2; j++) {                                              \
        float send = (lane & 4) ? acc[j] : acc[j + 2];                         \
        float recv = __shfl_xor_sync(0xffffffffu, send, 4);                    \
        acc[j] = ((lane & 4) ? acc[j + 2] : acc[j]) + recv;                    \
    }                                                                          \
    {                                                                          \
        float send = (lane & 2) ? acc[0] : acc[1];                             \
        float recv = __shfl_xor_sync(0xffffffffu, send, 2);                    \
        acc[0] = ((lane & 2) ? acc[1] : acc[0]) + recv;                        \
    }                                                                          \
    int dim = (half << 3) | (((sub >> 3) & 1) << 2) | (((sub >> 2) & 1) << 1) | ((sub >> 1) & 1); \
    float inv = (den > 0.f) ? (2.0f / den) : 0.f;                              \
    float val = lr001(acc[0] * inv);

// inverse lane permutation: lane (within half-warp) holding component k
#define INV_LANE(k) ((((k) >> 2) & 1) * 8 + (((k) >> 1) & 1) * 4 + ((k) & 1) * 2 + (((k) >> 3) & 1))

// ---------------------------------------------------------------------------
// accrank: blocks [0,nbA) do layer-1 accumulate + fused layer-2 projection;
// remaining blocks do rank on layer 2 (independent of layer-1 data).
// ---------------------------------------------------------------------------
__global__ __launch_bounds__(256) void accrank_kernel(
        const float* __restrict__ attn,
        const float* __restrict__ Ws2, const float* __restrict__ bs2,
        const float* __restrict__ Wd2, const float* __restrict__ bd2,
        const int* __restrict__ dst2, int E2, int N, int nbA) {
    if (blockIdx.x >= nbA) {                 // whole block takes rank role
        rank_edges(dst2, E2, g_cnt2, blockIdx.x - nbA);
        return;
    }
    __shared__ float sat[D];
    __shared__ float sWs[D * D], sWd[D * D], sbs[D], sbd[D];
    if (threadIdx.x < D) {
        sat[threadIdx.x] = attn[threadIdx.x];
        sbs[threadIdx.x] = bs2[threadIdx.x];
        sbd[threadIdx.x] = bd2[threadIdx.x];
    }
    if (threadIdx.x < D * D) { sWs[threadIdx.x] = Ws2[threadIdx.x]; sWd[threadIdx.x] = Wd2[threadIdx.x]; }
    __syncthreads();

    ACCUM_BODY(g_fsh, g_fd)

    // fused layer-2 projection: component k of h2 lives on lane INV_LANE(k)
    float os = sbs[sub], od = sbd[sub];
#pragma unroll
    for (int k = 0; k < D; k++) {
        float h2k = __shfl_sync(0xffffffffu, val, (lane & 16) + INV_LANE(k));
        os = fmaf(h2k, sWs[k * D + sub], os);
        od = fmaf(h2k, sWd[k * D + sub], od);
    }
    float osn = __shfl_xor_sync(0xffffffffu, os, 1);
    if (node < N) {
        if (!(sub & 1)) {
            __half2 t = __floats2half2_rn(os, osn);
            reinterpret_cast<unsigned*>(g_fshB)[node * 8 + (sub >> 1)] = *reinterpret_cast<unsigned*>(&t);
        }
        reinterpret_cast<float*>(g_fdB)[node * D + sub] = od;
    }
}

// layer-2 accumulate: writes final output
__global__ __launch_bounds__(256) void accum2_kernel(
        const float* __restrict__ attn, float* __restrict__ out, int N) {
    __shared__ float sat[D];
    if (threadIdx.x < D) sat[threadIdx.x] = attn[threadIdx.x];
    __syncthreads();

    ACCUM_BODY(g_fshB, g_fdB)

    if (node < N) out[node * D + dim] = val;
}

// ---------------------------------------------------------------------------
// launch
// ---------------------------------------------------------------------------
extern "C" void kernel_launch(void* const* d_in, const int* in_sizes, int n_in,
                              void* d_out, int out_size) {
    const float* emb  = (const float*)d_in[0];
    const int*   src1 = (const int*)d_in[1];
    const int*   dst1 = (const int*)d_in[2];
    const int*   src2 = (const int*)d_in[3];
    const int*   dst2 = (const int*)d_in[4];
    const float* Ws1  = (const float*)d_in[5];
    const float* bs1  = (const float*)d_in[6];
    const float* Wd1  = (const float*)d_in[7];
    const float* bd1  = (const float*)d_in[8];
    const float* at1  = (const float*)d_in[9];
    const float* Ws2  = (const float*)d_in[10];
    const float* bs2  = (const float*)d_in[11];
    const float* Wd2  = (const float*)d_in[12];
    const float* bd2  = (const float*)d_in[13];
    const float* at2  = (const float*)d_in[14];

    int N  = in_sizes[0] / D;
    int E1 = in_sizes[1];
    int E2 = in_sizes[3];

    int nbF  = (N + 255) / 256;
    int nbV1 = ((E1 + 7) / 8 + 255) / 256;     // 8 edges/thread
    int nbV2 = ((E2 + 7) / 8 + 255) / 256;
    int nbA  = (N + 15) / 16;                  // 2 nodes/warp
    int nbS  = (N + SCAN_BLK - 1) / SCAN_BLK;

    // zero per-layer histograms + scan states (capturable memset nodes)
    void *p_cnt1, *p_cnt2, *p_st1, *p_st2;
    cudaGetSymbolAddress(&p_cnt1, g_cnt1);
    cudaGetSymbolAddress(&p_cnt2, g_cnt2);
    cudaGetSymbolAddress(&p_st1, g_state1);
    cudaGetSymbolAddress(&p_st2, g_state2);
    cudaMemsetAsync(p_cnt1, 0, (size_t)N * sizeof(int));
    cudaMemsetAsync(p_cnt2, 0, (size_t)N * sizeof(int));
    cudaMemsetAsync(p_st1, 0, 1024 * sizeof(unsigned));
    cudaMemsetAsync(p_st2, 0, 1024 * sizeof(unsigned));

    // ---- pipeline with heterogeneous overlap ----
    featrank_kernel<<<nbF + nbV1, 256>>>(emb, Ws1, bs1, Wd1, bd1, dst1, E1, N, nbF);
    scan_kernel<<<nbS, SCAN_BLK>>>(N, E1, 0);
    scatter_kernel<<<nbV1, 256>>>(src1, dst1, E1);
    accrank_kernel<<<nbA + nbV2, 256>>>(at1, Ws2, bs2, Wd2, bd2, dst2, E2, N, nbA);
    scan_kernel<<<nbS, SCAN_BLK>>>(N, E2, 1);
    scatter_kernel<<<nbV2, 256>>>(src2, dst2, E2);
    accum2_kernel<<<nbA, 256>>>(at2, (float*)d_out, N);
}